// round 7
// baseline (speedup 1.0000x reference)
#include <cuda_runtime.h>

#define NMAX  256
#define EDGES 2048
#define HDIM  64
#define EMBED 39
#define NT    512
#define XS    66          // even stride: 8B-aligned lane pairs, conflict-free

#define FMA_F32X2(d, a, b, c) \
  asm("fma.rn.f32x2 %0, %1, %2, %3;" : "=l"(d) : "l"(a), "l"(b), "l"(c))

__device__ __forceinline__ int cmap(int c) { return ((c & 31) << 1) | (c >> 5); }

struct Smem {
  float xsA[NMAX * XS];            // 67584 B
  float xsB[NMAX * XS];            // 67584 B
  float Ws[HDIM * HDIM];           // 16384 B
  unsigned int epack[EDGES];       // src | dst<<8 | valid<<16
  unsigned long long esorted[EDGES]; // coef_bits<<32 | src  (valid edges, by dst)
  unsigned long long skey64[NMAX];
  int   hist[NMAX];
  int   ofs[NMAX + 1];
  int   cursor[NMAX];
  float dinv[NMAX];
  int   newid[NMAX];
  float rsum[2 * HDIM];
  float bvec[HDIM];
  float pvec[HDIM];
  float h1[HDIM];
  float red[4];
};

__device__ __forceinline__ unsigned long long make_key(float s, int idx) {
  unsigned bits = __float_as_uint(s);
  unsigned m = (bits & 0x80000000u) ? ~bits : (bits | 0x80000000u);
  unsigned hi = ~m;
  return ((unsigned long long)hi << 32) | (unsigned)idx;
}
__device__ __forceinline__ float key_score(unsigned long long k) {
  unsigned m = ~(unsigned)(k >> 32);
  unsigned bits = (m & 0x80000000u) ? (m ^ 0x80000000u) : ~m;
  return __uint_as_float(bits);
}

__device__ __forceinline__ unsigned long long ce_shfl(unsigned long long k, int j, bool takeMin) {
  unsigned long long o = __shfl_xor_sync(0xffffffffu, k, j);
  unsigned long long mn = (o < k) ? o : k;
  unsigned long long mx = (o < k) ? k : o;
  return takeMin ? mn : mx;
}

__device__ __forceinline__ void smem_ce(unsigned long long* a, int tid, int j, int ksz) {
  if (tid < 128) {
    int low = tid & (j - 1);
    int i = ((tid ^ low) << 1) | low;
    int p = i | j;
    unsigned long long x = a[i], y = a[p];
    bool asc = ((i & ksz) == 0);
    bool sw = asc ? (x > y) : (x < y);
    if (sw) { a[i] = y; a[p] = x; }
  }
}

// epilogue: store interleaved (col c -> word (c&31)*2 + (c>>5))
__device__ __forceinline__ void gemm_store(float* __restrict__ tmp, int row, int hbit,
                                           const unsigned long long* acc) {
#pragma unroll
  for (int j0 = 0; j0 < 8; ++j0) {
#pragma unroll
    for (int t = 0; t < 2; ++t) {
      unsigned lo, hi;
      asm("mov.b64 {%0, %1}, %2;" : "=r"(lo), "=r"(hi) : "l"(acc[j0 * 2 + t]));
      int c0 = j0 * 4 + t * 2;
      tmp[row * XS + c0 * 2 + hbit]       = __uint_as_float(lo);
      tmp[row * XS + (c0 + 1) * 2 + hbit] = __uint_as_float(hi);
    }
  }
}

// layer 0: x rows straight from GMEM registers
__device__ __forceinline__ void gemm_first(const float* __restrict__ xg,
                                           float* __restrict__ tmp,
                                           const float* __restrict__ Ws, int tid) {
  const int row  = tid >> 1;
  const int hbit = tid & 1;
  const int half = hbit << 5;
  float xr[EMBED];
#pragma unroll
  for (int k = 0; k < EMBED; ++k) xr[k] = xg[row * EMBED + k];
  unsigned long long acc[16];
#pragma unroll
  for (int i = 0; i < 16; ++i) acc[i] = 0ull;
#pragma unroll 3
  for (int k = 0; k < EMBED; ++k) {
    unsigned long long xp;
    asm("mov.b64 %0, {%1, %1};" : "=l"(xp) : "r"(__float_as_uint(xr[k])));
#pragma unroll
    for (int j0 = 0; j0 < 8; ++j0) {
      const ulonglong2 w2 = *reinterpret_cast<const ulonglong2*>(&Ws[k * HDIM + half + j0 * 4]);
      FMA_F32X2(acc[j0 * 2],     xp, w2.x, acc[j0 * 2]);
      FMA_F32X2(acc[j0 * 2 + 1], xp, w2.y, acc[j0 * 2 + 1]);
    }
  }
  gemm_store(tmp, row, hbit, acc);
}

// layers 1,2: interleaved input, paired k / k+32 via one LDS.64
__device__ __forceinline__ void gemm_ilv(const float* __restrict__ cur,
                                         float* __restrict__ tmp,
                                         const float* __restrict__ Ws, int n, int tid) {
  const int row  = tid >> 1;
  const int hbit = tid & 1;
  const int half = hbit << 5;
  if (row >= n) return;
  unsigned long long acc[16];
#pragma unroll
  for (int i = 0; i < 16; ++i) acc[i] = 0ull;
#pragma unroll 4
  for (int k2 = 0; k2 < 32; ++k2) {
    const float2 xv = *reinterpret_cast<const float2*>(&cur[row * XS + (k2 << 1)]);
    unsigned long long xa, xb;
    asm("mov.b64 %0, {%1, %1};" : "=l"(xa) : "r"(__float_as_uint(xv.x)));
    asm("mov.b64 %0, {%1, %1};" : "=l"(xb) : "r"(__float_as_uint(xv.y)));
#pragma unroll
    for (int j0 = 0; j0 < 8; ++j0) {
      const ulonglong2 wa = *reinterpret_cast<const ulonglong2*>(&Ws[k2 * HDIM + half + j0 * 4]);
      const ulonglong2 wb = *reinterpret_cast<const ulonglong2*>(&Ws[(k2 + 32) * HDIM + half + j0 * 4]);
      FMA_F32X2(acc[j0 * 2],     xa, wa.x, acc[j0 * 2]);
      FMA_F32X2(acc[j0 * 2 + 1], xa, wa.y, acc[j0 * 2 + 1]);
      FMA_F32X2(acc[j0 * 2],     xb, wb.x, acc[j0 * 2]);
      FMA_F32X2(acc[j0 * 2 + 1], xb, wb.y, acc[j0 * 2 + 1]);
    }
  }
  gemm_store(tmp, row, hbit, acc);
}

__global__ __launch_bounds__(NT)
void gnn_kernel(const float* __restrict__ x,
                const int* __restrict__ ei,
                const float* __restrict__ W1, const float* __restrict__ b1, const float* __restrict__ p1,
                const float* __restrict__ W2, const float* __restrict__ b2, const float* __restrict__ p2,
                const float* __restrict__ W3, const float* __restrict__ b3, const float* __restrict__ p3,
                const float* __restrict__ lW1, const float* __restrict__ lb1,
                const float* __restrict__ lW2, const float* __restrict__ lb2,
                const float* __restrict__ lW3, const float* __restrict__ lb3,
                float* __restrict__ out) {
  extern __shared__ char smraw[];
  Smem& S = *reinterpret_cast<Smem*>(smraw);
  const int b    = blockIdx.x;
  const int tid  = threadIdx.x;
  const int lane = tid & 31;
  const int wid  = tid >> 5;

  // ---- vectorized edge load: 4 edges per thread ----
  const int* eb = ei + (size_t)b * 2 * EDGES;
  {
    const int4 s4 = *reinterpret_cast<const int4*>(&eb[tid * 4]);
    const int4 d4 = *reinterpret_cast<const int4*>(&eb[EDGES + tid * 4]);
    uint4 w;
    w.x = ((unsigned)s4.x & 255u) | (((unsigned)d4.x & 255u) << 8) | (1u << 16);
    w.y = ((unsigned)s4.y & 255u) | (((unsigned)d4.y & 255u) << 8) | (1u << 16);
    w.z = ((unsigned)s4.z & 255u) | (((unsigned)d4.z & 255u) << 8) | (1u << 16);
    w.w = ((unsigned)s4.w & 255u) | (((unsigned)d4.w & 255u) << 8) | (1u << 16);
    *reinterpret_cast<uint4*>(&S.epack[tid * 4]) = w;
  }
  if (tid < 2 * HDIM) S.rsum[tid] = 0.f;

  const float* xg = x + (size_t)b * NMAX * EMBED;
  float* cur = S.xsA;
  float* tmp = S.xsB;
  int n = NMAX;
  const int kk[3] = {205, 164, 132};
  const float* Wl[3] = {W1, W2, W3};
  const float* bl[3] = {b1, b2, b3};
  const float* pl[3] = {p1, p2, p3};

  for (int layer = 0; layer < 3; ++layer) {
    const int KD = (layer == 0) ? EMBED : HDIM;
    // ---- stage weights / bias / p / hist clear ----
    for (int idx = tid; idx < (KD * HDIM) / 4; idx += NT)
      reinterpret_cast<float4*>(S.Ws)[idx] = reinterpret_cast<const float4*>(Wl[layer])[idx];
    if (tid >= 64 && tid < 128) { int j = tid - 64; S.bvec[j] = bl[layer][j]; S.pvec[j] = pl[layer][j]; }
    if (tid >= 128 && tid < 384) S.hist[tid - 128] = 0;
    if (wid == 14) {  // pscale = 1/||p||
      float a = pl[layer][lane], c2 = pl[layer][lane + 32];
      float s2 = a * a + c2 * c2;
#pragma unroll
      for (int o = 16; o; o >>= 1) s2 += __shfl_xor_sync(0xffffffffu, s2, o);
      if (lane == 0) S.red[0] = rsqrtf(s2);
    }
    __syncthreads();

    // ---- GEMM (into tmp) + histogram of valid edges (independent) ----
    if (layer == 0) gemm_first(xg, tmp, S.Ws, tid);
    else            gemm_ilv(cur, tmp, S.Ws, n, tid);
#pragma unroll
    for (int e = tid; e < EDGES; e += NT) {
      unsigned u = S.epack[e];
      if (u >> 16) atomicAdd(&S.hist[(u >> 8) & 255], 1);
    }
    __syncthreads();

    // ---- single-warp scan -> ofs / cursor / dinv ----
    if (wid == 0) {
      int c[8];
#pragma unroll
      for (int q = 0; q < 8; ++q) c[q] = S.hist[lane * 8 + q];
      int sum = 0;
#pragma unroll
      for (int q = 0; q < 8; ++q) sum += c[q];
      int incl = sum;
#pragma unroll
      for (int o = 1; o < 32; o <<= 1) {
        int t = __shfl_up_sync(0xffffffffu, incl, o);
        if (lane >= o) incl += t;
      }
      int run = incl - sum;
#pragma unroll
      for (int q = 0; q < 8; ++q) {
        int node = lane * 8 + q;
        S.ofs[node]    = run;
        S.cursor[node] = run;
        S.dinv[node]   = rsqrtf(1.0f + (float)c[q]);
        run += c[q];
      }
      if (lane == 31) S.ofs[NMAX] = run;
    }
    __syncthreads();

    // ---- scatter valid edges with embedded coef, sorted by dst ----
#pragma unroll
    for (int e = tid; e < EDGES; e += NT) {
      unsigned u = S.epack[e];
      if (u >> 16) {
        int sN = u & 255;
        int d  = (u >> 8) & 255;
        int pos = atomicAdd(&S.cursor[d], 1);
        S.esorted[pos] = ((unsigned long long)__float_as_uint(S.dinv[sN]) << 32) | (unsigned)sN;
      }
    }
    __syncthreads();

    // ---- aggregation (warp/node) + relu + fused score ----
    const float pscale = S.red[0];
    for (int i = wid; i < n; i += NT / 32) {
      const int beg = S.ofs[i], end = S.ofs[i + 1];
      const float di = S.dinv[i];
      unsigned long long acc = 0ull;
      int p = beg;
      unsigned long long enext = (p < end) ? S.esorted[p] : 0ull;
      while (p < end) {
        const unsigned long long e = enext;
        ++p;
        if (p < end) enext = S.esorted[p];  // prefetch next (independent of hv)
        const int sN = (int)(e & 255u);
        unsigned long long cp;
        asm("mov.b64 %0, {%1, %1};" : "=l"(cp) : "r"((unsigned)(e >> 32)));
        const unsigned long long hv =
            *reinterpret_cast<const unsigned long long*>(&tmp[sN * XS + (lane << 1)]);
        FMA_F32X2(acc, cp, hv, acc);
      }
      unsigned a0u, a1u;
      asm("mov.b64 {%0, %1}, %2;" : "=r"(a0u), "=r"(a1u) : "l"(acc));
      const float2 hself = *reinterpret_cast<const float2*>(&tmp[i * XS + (lane << 1)]);
      const float idg = di * di;
      float v0 = fmaxf(__uint_as_float(a0u) * di + hself.x * idg + S.bvec[lane], 0.f);
      float v1 = fmaxf(__uint_as_float(a1u) * di + hself.y * idg + S.bvec[lane + 32], 0.f);
      cur[i * XS + (lane << 1)]     = v0;
      cur[i * XS + (lane << 1) + 1] = v1;
      float sc = v0 * S.pvec[lane] + v1 * S.pvec[lane + 32];
#pragma unroll
      for (int o = 16; o; o >>= 1) sc += __shfl_xor_sync(0xffffffffu, sc, o);
      if (lane == 0) S.skey64[i] = make_key(tanhf(sc * pscale), i);
    }
    for (int i = n + tid; i < NMAX; i += NT) S.skey64[i] = make_key(-1e30f, i);
    if (tid < NMAX) S.newid[tid] = -1;
    __syncthreads();

    // ---- bitonic sort 256 u64 keys (warp shuffle + smem merge) ----
    if (tid < NMAX) {
      unsigned long long k = S.skey64[tid];
#pragma unroll
      for (int ksz = 2; ksz <= 32; ksz <<= 1)
#pragma unroll
        for (int j = ksz >> 1; j > 0; j >>= 1)
          k = ce_shfl(k, j, ((tid & j) == 0) == ((tid & ksz) == 0));
      S.skey64[tid] = k;
    }
    __syncthreads();
#pragma unroll
    for (int ksz = 64; ksz <= 256; ksz <<= 1) {
      for (int j = ksz >> 1; j >= 32; j >>= 1) {
        smem_ce(S.skey64, tid, j, ksz);
        __syncthreads();
      }
      if (tid < NMAX) {
        unsigned long long k = S.skey64[tid];
        const bool asc = ((tid & ksz) == 0);
#pragma unroll
        for (int j = 16; j > 0; j >>= 1)
          k = ce_shfl(k, j, ((tid & j) == 0) == asc);
        S.skey64[tid] = k;
      }
      __syncthreads();
    }

    const int kcur = kk[layer];
    if (tid < kcur) {
      int old = (int)(S.skey64[tid] & 0xffffffffull);
      S.newid[old] = tid;
    }
    __syncthreads();

    // ---- pooled rows -> tmp (scaled); remap edges ----
    for (int r = wid; r < kcur; r += NT / 32) {
      unsigned long long key = S.skey64[r];
      int old = (int)(key & 0xffffffffull);
      float v = key_score(key);
      float2 h2 = *reinterpret_cast<const float2*>(&cur[old * XS + (lane << 1)]);
      tmp[r * XS + (lane << 1)]     = h2.x * v;
      tmp[r * XS + (lane << 1) + 1] = h2.y * v;
    }
    if (layer < 2) {
#pragma unroll
      for (int e = tid; e < EDGES; e += NT) {
        unsigned u = S.epack[e];
        int sN = u & 255, d = (u >> 8) & 255;
        int valid = (int)(u >> 16);
        int ns = S.newid[sN], nd = S.newid[d];
        int nv = (valid && ns >= 0 && nd >= 0) ? 1 : 0;
        if (ns < 0) ns = 0;
        if (nd < 0) nd = 0;
        S.epack[e] = (unsigned)ns | ((unsigned)nd << 8) | ((unsigned)nv << 16);
      }
    }
    __syncthreads();

    // ---- readout: warp per column ----
    for (int c = wid; c < HDIM; c += NT / 32) {
      const int off = cmap(c);
      float m = -1e30f, sm = 0.f;
      for (int r = lane; r < kcur; r += 32) {
        float v = tmp[r * XS + off];
        m = fmaxf(m, v);
        sm += v;
      }
#pragma unroll
      for (int o = 16; o; o >>= 1) {
        m  = fmaxf(m, __shfl_xor_sync(0xffffffffu, m, o));
        sm += __shfl_xor_sync(0xffffffffu, sm, o);
      }
      if (lane == 0) {
        S.rsum[c]        += m;
        S.rsum[HDIM + c] += sm / (float)kcur;
      }
    }
    float* t = cur; cur = tmp; tmp = t;
    n = kcur;
    __syncthreads();
  }

  // ---- MLP head: 128 -> 64 (256 threads) -> 32 -> 1 ----
  if (tid < 256) {
    int j = tid >> 2, q = tid & 3;
    float a = 0.f;
#pragma unroll 8
    for (int i = q * 32; i < q * 32 + 32; ++i) a += S.rsum[i] * lW1[i * 64 + j];
    a += __shfl_xor_sync(0xffffffffu, a, 1);
    a += __shfl_xor_sync(0xffffffffu, a, 2);
    if (q == 0) S.h1[j] = fmaxf(a + lb1[j], 0.f);
  }
  __syncthreads();
  if (tid < 32) {
    float a = lb2[tid];
#pragma unroll 8
    for (int j = 0; j < 64; ++j) a += S.h1[j] * lW2[j * 32 + tid];
    float h2 = fmaxf(a, 0.f);
    float v = h2 * lW3[tid];
#pragma unroll
    for (int o = 16; o; o >>= 1) v += __shfl_xor_sync(0xffffffffu, v, o);
    if (tid == 0) out[b] = 1.0f / (1.0f + expf(-(v + lb3[0])));
  }
}

extern "C" void kernel_launch(void* const* d_in, const int* in_sizes, int n_in,
                              void* d_out, int out_size) {
  const float* x   = (const float*)d_in[0];
  const int*   ei  = (const int*)d_in[1];
  const float* W1  = (const float*)d_in[2];
  const float* b1  = (const float*)d_in[3];
  const float* p1  = (const float*)d_in[4];
  const float* W2  = (const float*)d_in[5];
  const float* b2  = (const float*)d_in[6];
  const float* p2  = (const float*)d_in[7];
  const float* W3  = (const float*)d_in[8];
  const float* b3  = (const float*)d_in[9];
  const float* p3  = (const float*)d_in[10];
  const float* lW1 = (const float*)d_in[11];
  const float* lb1 = (const float*)d_in[12];
  const float* lW2 = (const float*)d_in[13];
  const float* lb2 = (const float*)d_in[14];
  const float* lW3 = (const float*)d_in[15];
  const float* lb3 = (const float*)d_in[16];
  float* out = (float*)d_out;

  const int B = in_sizes[0] / (NMAX * EMBED);
  const size_t sm = sizeof(Smem);
  cudaFuncSetAttribute(gnn_kernel, cudaFuncAttributeMaxDynamicSharedMemorySize, (int)sm);
  gnn_kernel<<<B, NT, sm>>>(x, ei, W1, b1, p1, W2, b2, p2, W3, b3, p3,
                            lW1, lb1, lW2, lb2, lW3, lb3, out);
}

// round 8
// speedup vs baseline: 1.2311x; 1.2311x over previous
#include <cuda_runtime.h>

#define NMAX  256
#define EDGES 2048
#define HDIM  64
#define EMBED 39
#define NT    512
#define XS    66          // even stride: 8B-aligned lane pairs, conflict-free

#define FMA_F32X2(d, a, b, c) \
  asm("fma.rn.f32x2 %0, %1, %2, %3;" : "=l"(d) : "l"(a), "l"(b), "l"(c))
#define DUP_F32(d, f) \
  asm("mov.b64 %0, {%1, %1};" : "=l"(d) : "r"(__float_as_uint(f)))

__device__ __forceinline__ int cmap(int c) { return ((c & 31) << 1) | (c >> 5); }

struct Smem {
  float xsA[NMAX * XS];            // 67584 B
  float xsB[NMAX * XS];            // 67584 B
  float Ws[HDIM * HDIM];           // 16384 B
  unsigned int epack[EDGES];       // src | dst<<8 | valid<<16
  unsigned int esorted[EDGES];     // valid edges by dst (src id only)
  unsigned long long skey64[NMAX];
  int   hist[NMAX];
  int   ofs[NMAX + 1];
  int   cursor[NMAX];
  float dinv[NMAX];
  int   newid[NMAX];
  float rsum[2 * HDIM];
  float bvec[HDIM];
  float pvec[HDIM];
  float h1[HDIM];
  float red[4];
};

__device__ __forceinline__ unsigned long long make_key(float s, int idx) {
  unsigned bits = __float_as_uint(s);
  unsigned m = (bits & 0x80000000u) ? ~bits : (bits | 0x80000000u);
  unsigned hi = ~m;
  return ((unsigned long long)hi << 32) | (unsigned)idx;
}
__device__ __forceinline__ float key_score(unsigned long long k) {
  unsigned m = ~(unsigned)(k >> 32);
  unsigned bits = (m & 0x80000000u) ? (m ^ 0x80000000u) : ~m;
  return __uint_as_float(bits);
}

__device__ __forceinline__ unsigned long long ce_shfl(unsigned long long k, int j, bool takeMin) {
  unsigned long long o = __shfl_xor_sync(0xffffffffu, k, j);
  unsigned long long mn = (o < k) ? o : k;
  unsigned long long mx = (o < k) ? k : o;
  return takeMin ? mn : mx;
}

__device__ __forceinline__ void smem_ce(unsigned long long* a, int tid, int j, int ksz) {
  if (tid < 128) {
    int low = tid & (j - 1);
    int i = ((tid ^ low) << 1) | low;
    int p = i | j;
    unsigned long long x = a[i], y = a[p];
    bool asc = ((i & ksz) == 0);
    bool sw = asc ? (x > y) : (x < y);
    if (sw) { a[i] = y; a[p] = x; }
  }
}

// ---- GEMM 4 rows x 8 cols per thread; interleaved output ----
// tid -> colgrp = tid&7 (cols cbase..cbase+8), rowgrp = tid>>3 (rows row0..row0+4)
__device__ __forceinline__ void gemm_epilogue(float* __restrict__ tmp, int row0, int n,
                                              int chalf, int hbit,
                                              unsigned long long acc[4][4]) {
#pragma unroll
  for (int r = 0; r < 4; ++r) {
    const int row = row0 + r;
    if (row < n) {
#pragma unroll
      for (int cp = 0; cp < 4; ++cp) {
        unsigned lo, hi;
        asm("mov.b64 {%0, %1}, %2;" : "=r"(lo), "=r"(hi) : "l"(acc[r][cp]));
        const int c0 = chalf + 2 * cp;
        tmp[row * XS + c0 * 2 + hbit]       = __uint_as_float(lo);
        tmp[row * XS + (c0 + 1) * 2 + hbit] = __uint_as_float(hi);
      }
    }
  }
}

// layer 0: linear-layout input (K=39)
__device__ __forceinline__ void gemm_first(const float* __restrict__ cur,
                                           float* __restrict__ tmp,
                                           const float* __restrict__ Ws, int tid) {
  const int colgrp = tid & 7;
  const int row0   = (tid >> 3) * 4;
  const int cbase  = colgrp * 8;
  const int hbit   = colgrp >> 2;
  const int chalf  = (colgrp & 3) * 8;
  unsigned long long acc[4][4];
#pragma unroll
  for (int r = 0; r < 4; ++r)
#pragma unroll
    for (int cp = 0; cp < 4; ++cp) acc[r][cp] = 0ull;
#pragma unroll 3
  for (int k = 0; k < EMBED; ++k) {
    const ulonglong2 w0 = *reinterpret_cast<const ulonglong2*>(&Ws[k * HDIM + cbase]);
    const ulonglong2 w1 = *reinterpret_cast<const ulonglong2*>(&Ws[k * HDIM + cbase + 4]);
#pragma unroll
    for (int r = 0; r < 4; ++r) {
      unsigned long long xa;
      DUP_F32(xa, cur[(row0 + r) * XS + k]);
      FMA_F32X2(acc[r][0], xa, w0.x, acc[r][0]);
      FMA_F32X2(acc[r][1], xa, w0.y, acc[r][1]);
      FMA_F32X2(acc[r][2], xa, w1.x, acc[r][2]);
      FMA_F32X2(acc[r][3], xa, w1.y, acc[r][3]);
    }
  }
  gemm_epilogue(tmp, row0, NMAX, chalf, hbit, acc);
}

// layers 1,2: interleaved input (K=64); pair k2 / k2+32 via one LDS.64
__device__ __forceinline__ void gemm_ilv(const float* __restrict__ cur,
                                         float* __restrict__ tmp,
                                         const float* __restrict__ Ws, int n, int tid) {
  const int colgrp = tid & 7;
  const int row0   = (tid >> 3) * 4;
  const int cbase  = colgrp * 8;
  const int hbit   = colgrp >> 2;
  const int chalf  = (colgrp & 3) * 8;
  unsigned long long acc[4][4];
#pragma unroll
  for (int r = 0; r < 4; ++r)
#pragma unroll
    for (int cp = 0; cp < 4; ++cp) acc[r][cp] = 0ull;
#pragma unroll 4
  for (int k2 = 0; k2 < 32; ++k2) {
    const ulonglong2 wa0 = *reinterpret_cast<const ulonglong2*>(&Ws[k2 * HDIM + cbase]);
    const ulonglong2 wa1 = *reinterpret_cast<const ulonglong2*>(&Ws[k2 * HDIM + cbase + 4]);
    const ulonglong2 wb0 = *reinterpret_cast<const ulonglong2*>(&Ws[(k2 + 32) * HDIM + cbase]);
    const ulonglong2 wb1 = *reinterpret_cast<const ulonglong2*>(&Ws[(k2 + 32) * HDIM + cbase + 4]);
#pragma unroll
    for (int r = 0; r < 4; ++r) {
      const float2 xv = *reinterpret_cast<const float2*>(&cur[(row0 + r) * XS + (k2 << 1)]);
      unsigned long long xa, xb;
      DUP_F32(xa, xv.x);
      DUP_F32(xb, xv.y);
      FMA_F32X2(acc[r][0], xa, wa0.x, acc[r][0]);
      FMA_F32X2(acc[r][1], xa, wa0.y, acc[r][1]);
      FMA_F32X2(acc[r][2], xa, wa1.x, acc[r][2]);
      FMA_F32X2(acc[r][3], xa, wa1.y, acc[r][3]);
      FMA_F32X2(acc[r][0], xb, wb0.x, acc[r][0]);
      FMA_F32X2(acc[r][1], xb, wb0.y, acc[r][1]);
      FMA_F32X2(acc[r][2], xb, wb1.x, acc[r][2]);
      FMA_F32X2(acc[r][3], xb, wb1.y, acc[r][3]);
    }
  }
  gemm_epilogue(tmp, row0, n, chalf, hbit, acc);
}

__global__ __launch_bounds__(NT)
void gnn_kernel(const float* __restrict__ x,
                const int* __restrict__ ei,
                const float* __restrict__ W1, const float* __restrict__ b1, const float* __restrict__ p1,
                const float* __restrict__ W2, const float* __restrict__ b2, const float* __restrict__ p2,
                const float* __restrict__ W3, const float* __restrict__ b3, const float* __restrict__ p3,
                const float* __restrict__ lW1, const float* __restrict__ lb1,
                const float* __restrict__ lW2, const float* __restrict__ lb2,
                const float* __restrict__ lW3, const float* __restrict__ lb3,
                float* __restrict__ out) {
  extern __shared__ char smraw[];
  Smem& S = *reinterpret_cast<Smem*>(smraw);
  const int b    = blockIdx.x;
  const int tid  = threadIdx.x;
  const int lane = tid & 31;
  const int wid  = tid >> 5;

  // ---- vectorized edge load: 4 edges per thread ----
  const int* eb = ei + (size_t)b * 2 * EDGES;
  {
    const int4 s4 = *reinterpret_cast<const int4*>(&eb[tid * 4]);
    const int4 d4 = *reinterpret_cast<const int4*>(&eb[EDGES + tid * 4]);
    uint4 w;
    w.x = ((unsigned)s4.x & 255u) | (((unsigned)d4.x & 255u) << 8) | (1u << 16);
    w.y = ((unsigned)s4.y & 255u) | (((unsigned)d4.y & 255u) << 8) | (1u << 16);
    w.z = ((unsigned)s4.z & 255u) | (((unsigned)d4.z & 255u) << 8) | (1u << 16);
    w.w = ((unsigned)s4.w & 255u) | (((unsigned)d4.w & 255u) << 8) | (1u << 16);
    *reinterpret_cast<uint4*>(&S.epack[tid * 4]) = w;
  }
  // ---- stage x [256, 39] coalesced -> linear layout ----
  const float* xb = x + (size_t)b * NMAX * EMBED;
  for (int idx = tid; idx < NMAX * EMBED; idx += NT) {
    int r = idx / EMBED, c = idx - r * EMBED;
    S.xsA[r * XS + c] = xb[idx];
  }
  if (tid < 2 * HDIM) S.rsum[tid] = 0.f;

  float* cur = S.xsA;
  float* tmp = S.xsB;
  int n = NMAX;
  const int kk[3] = {205, 164, 132};
  const float* Wl[3] = {W1, W2, W3};
  const float* bl[3] = {b1, b2, b3};
  const float* pl[3] = {p1, p2, p3};

  for (int layer = 0; layer < 3; ++layer) {
    const int KD = (layer == 0) ? EMBED : HDIM;
    // ---- stage weights / bias / p / hist clear ----
    for (int idx = tid; idx < (KD * HDIM) / 4; idx += NT)
      reinterpret_cast<float4*>(S.Ws)[idx] = reinterpret_cast<const float4*>(Wl[layer])[idx];
    if (tid >= 64 && tid < 128) { int j = tid - 64; S.bvec[j] = bl[layer][j]; S.pvec[j] = pl[layer][j]; }
    if (tid >= 128 && tid < 384) S.hist[tid - 128] = 0;
    if (wid == 14) {  // pscale = 1/||p||
      float a = pl[layer][lane], c2 = pl[layer][lane + 32];
      float s2 = a * a + c2 * c2;
#pragma unroll
      for (int o = 16; o; o >>= 1) s2 += __shfl_xor_sync(0xffffffffu, s2, o);
      if (lane == 0) S.red[0] = rsqrtf(s2);
    }
    __syncthreads();

    // ---- GEMM (into tmp) + histogram of valid edges (independent work) ----
    if (layer == 0) gemm_first(cur, tmp, S.Ws, tid);
    else            gemm_ilv(cur, tmp, S.Ws, n, tid);
#pragma unroll
    for (int e = tid; e < EDGES; e += NT) {
      unsigned u = S.epack[e];
      if (u >> 16) atomicAdd(&S.hist[(u >> 8) & 255], 1);
    }
    __syncthreads();

    // ---- single-warp scan -> ofs / cursor / dinv ----
    if (wid == 0) {
      int c[8];
#pragma unroll
      for (int q = 0; q < 8; ++q) c[q] = S.hist[lane * 8 + q];
      int sum = 0;
#pragma unroll
      for (int q = 0; q < 8; ++q) sum += c[q];
      int incl = sum;
#pragma unroll
      for (int o = 1; o < 32; o <<= 1) {
        int t = __shfl_up_sync(0xffffffffu, incl, o);
        if (lane >= o) incl += t;
      }
      int run = incl - sum;
#pragma unroll
      for (int q = 0; q < 8; ++q) {
        int node = lane * 8 + q;
        S.ofs[node]    = run;
        S.cursor[node] = run;
        S.dinv[node]   = rsqrtf(1.0f + (float)c[q]);
        run += c[q];
      }
      if (lane == 31) S.ofs[NMAX] = run;
    }
    __syncthreads();

    // ---- scatter valid edges (src only), sorted by dst ----
#pragma unroll
    for (int e = tid; e < EDGES; e += NT) {
      unsigned u = S.epack[e];
      if (u >> 16) {
        int d = (u >> 8) & 255;
        int pos = atomicAdd(&S.cursor[d], 1);
        S.esorted[pos] = u & 255u;
      }
    }
    __syncthreads();

    // ---- aggregation (warp/node) + relu + fused score ----
    const float pscale = S.red[0];
    for (int i = wid; i < n; i += NT / 32) {
      const int beg = S.ofs[i], end = S.ofs[i + 1];
      const float di = S.dinv[i];
      unsigned long long acc = 0ull;
      for (int p = beg; p < end; ++p) {
        const int sN = S.esorted[p];
        unsigned long long cp;
        DUP_F32(cp, S.dinv[sN]);
        const unsigned long long hv =
            *reinterpret_cast<const unsigned long long*>(&tmp[sN * XS + (lane << 1)]);
        FMA_F32X2(acc, cp, hv, acc);
      }
      unsigned a0u, a1u;
      asm("mov.b64 {%0, %1}, %2;" : "=r"(a0u), "=r"(a1u) : "l"(acc));
      const float2 hself = *reinterpret_cast<const float2*>(&tmp[i * XS + (lane << 1)]);
      const float idg = di * di;
      float v0 = fmaxf(__uint_as_float(a0u) * di + hself.x * idg + S.bvec[lane], 0.f);
      float v1 = fmaxf(__uint_as_float(a1u) * di + hself.y * idg + S.bvec[lane + 32], 0.f);
      cur[i * XS + (lane << 1)]     = v0;
      cur[i * XS + (lane << 1) + 1] = v1;
      float sc = v0 * S.pvec[lane] + v1 * S.pvec[lane + 32];
#pragma unroll
      for (int o = 16; o; o >>= 1) sc += __shfl_xor_sync(0xffffffffu, sc, o);
      if (lane == 0) S.skey64[i] = make_key(tanhf(sc * pscale), i);
    }
    for (int i = n + tid; i < NMAX; i += NT) S.skey64[i] = make_key(-1e30f, i);
    if (tid < NMAX) S.newid[tid] = -1;
    __syncthreads();

    // ---- bitonic sort 256 u64 keys (warp shuffle + smem merge) ----
    if (tid < NMAX) {
      unsigned long long k = S.skey64[tid];
#pragma unroll
      for (int ksz = 2; ksz <= 32; ksz <<= 1)
#pragma unroll
        for (int j = ksz >> 1; j > 0; j >>= 1)
          k = ce_shfl(k, j, ((tid & j) == 0) == ((tid & ksz) == 0));
      S.skey64[tid] = k;
    }
    __syncthreads();
#pragma unroll
    for (int ksz = 64; ksz <= 256; ksz <<= 1) {
      for (int j = ksz >> 1; j >= 32; j >>= 1) {
        smem_ce(S.skey64, tid, j, ksz);
        __syncthreads();
      }
      if (tid < NMAX) {
        unsigned long long k = S.skey64[tid];
        const bool asc = ((tid & ksz) == 0);
#pragma unroll
        for (int j = 16; j > 0; j >>= 1)
          k = ce_shfl(k, j, ((tid & j) == 0) == asc);
        S.skey64[tid] = k;
      }
      __syncthreads();
    }

    const int kcur = kk[layer];
    if (tid < kcur) {
      int old = (int)(S.skey64[tid] & 0xffffffffull);
      S.newid[old] = tid;
    }
    __syncthreads();

    // ---- pooled rows -> tmp (scaled); remap edges ----
    for (int r = wid; r < kcur; r += NT / 32) {
      unsigned long long key = S.skey64[r];
      int old = (int)(key & 0xffffffffull);
      float v = key_score(key);
      float2 h2 = *reinterpret_cast<const float2*>(&cur[old * XS + (lane << 1)]);
      tmp[r * XS + (lane << 1)]     = h2.x * v;
      tmp[r * XS + (lane << 1) + 1] = h2.y * v;
    }
    if (layer < 2) {
#pragma unroll
      for (int e = tid; e < EDGES; e += NT) {
        unsigned u = S.epack[e];
        int sN = u & 255, d = (u >> 8) & 255;
        int valid = (int)(u >> 16);
        int ns = S.newid[sN], nd = S.newid[d];
        int nv = (valid && ns >= 0 && nd >= 0) ? 1 : 0;
        if (ns < 0) ns = 0;
        if (nd < 0) nd = 0;
        S.epack[e] = (unsigned)ns | ((unsigned)nd << 8) | ((unsigned)nv << 16);
      }
    }
    __syncthreads();

    // ---- readout: warp per column ----
    for (int c = wid; c < HDIM; c += NT / 32) {
      const int off = cmap(c);
      float m = -1e30f, sm = 0.f;
      for (int r = lane; r < kcur; r += 32) {
        float v = tmp[r * XS + off];
        m = fmaxf(m, v);
        sm += v;
      }
#pragma unroll
      for (int o = 16; o; o >>= 1) {
        m  = fmaxf(m, __shfl_xor_sync(0xffffffffu, m, o));
        sm += __shfl_xor_sync(0xffffffffu, sm, o);
      }
      if (lane == 0) {
        S.rsum[c]        += m;
        S.rsum[HDIM + c] += sm / (float)kcur;
      }
    }
    float* t = cur; cur = tmp; tmp = t;
    n = kcur;
    __syncthreads();
  }

  // ---- MLP head: 128 -> 64 (256 threads) -> 32 -> 1 ----
  if (tid < 256) {
    int j = tid >> 2, q = tid & 3;
    float a = 0.f;
#pragma unroll 8
    for (int i = q * 32; i < q * 32 + 32; ++i) a += S.rsum[i] * lW1[i * 64 + j];
    a += __shfl_xor_sync(0xffffffffu, a, 1);
    a += __shfl_xor_sync(0xffffffffu, a, 2);
    if (q == 0) S.h1[j] = fmaxf(a + lb1[j], 0.f);
  }
  __syncthreads();
  if (tid < 32) {
    float a = lb2[tid];
#pragma unroll 8
    for (int j = 0; j < 64; ++j) a += S.h1[j] * lW2[j * 32 + tid];
    float h2 = fmaxf(a, 0.f);
    float v = h2 * lW3[tid];
#pragma unroll
    for (int o = 16; o; o >>= 1) v += __shfl_xor_sync(0xffffffffu, v, o);
    if (tid == 0) out[b] = 1.0f / (1.0f + expf(-(v + lb3[0])));
  }
}

extern "C" void kernel_launch(void* const* d_in, const int* in_sizes, int n_in,
                              void* d_out, int out_size) {
  const float* x   = (const float*)d_in[0];
  const int*   ei  = (const int*)d_in[1];
  const float* W1  = (const float*)d_in[2];
  const float* b1  = (const float*)d_in[3];
  const float* p1  = (const float*)d_in[4];
  const float* W2  = (const float*)d_in[5];
  const float* b2  = (const float*)d_in[6];
  const float* p2  = (const float*)d_in[7];
  const float* W3  = (const float*)d_in[8];
  const float* b3  = (const float*)d_in[9];
  const float* p3  = (const float*)d_in[10];
  const float* lW1 = (const float*)d_in[11];
  const float* lb1 = (const float*)d_in[12];
  const float* lW2 = (const float*)d_in[13];
  const float* lb2 = (const float*)d_in[14];
  const float* lW3 = (const float*)d_in[15];
  const float* lb3 = (const float*)d_in[16];
  float* out = (float*)d_out;

  const int B = in_sizes[0] / (NMAX * EMBED);
  const size_t sm = sizeof(Smem);
  cudaFuncSetAttribute(gnn_kernel, cudaFuncAttributeMaxDynamicSharedMemorySize, (int)sm);
  gnn_kernel<<<B, NT, sm>>>(x, ei, W1, b1, p1, W2, b2, p2, W3, b3, p3,
                            lW1, lb1, lW2, lb2, lW3, lb3, out);
}

// round 11
// speedup vs baseline: 1.6535x; 1.3431x over previous
#include <cuda_runtime.h>

#define NMAX  256
#define EDGES 2048
#define HDIM  64
#define EMBED 39
#define NT    1024
#define XS    68          // 272B rows: 16B-aligned float4 slots, plain layout

#define FMA_F32X2(d, a, b, c) \
  asm("fma.rn.f32x2 %0, %1, %2, %3;" : "=l"(d) : "l"(a), "l"(b), "l"(c))
#define DUP_F32(d, f) \
  asm("mov.b64 %0, {%1, %1};" : "=l"(d) : "r"(__float_as_uint(f)))

struct Smem {
  float xsA[NMAX * XS];            // 69632 B (16B aligned)
  float xsB[NMAX * XS];            // 69632 B
  float Ws[HDIM * HDIM];           // 16384 B
  unsigned int epack[EDGES];       // src | dst<<8 | valid<<16
  unsigned int esorted[EDGES];     // valid edges by dst (src id only)
  unsigned long long skey64[NMAX];
  int   hist[NMAX];
  int   ofs[NMAX + 1];
  int   cursor[NMAX];
  float dinv[NMAX];
  int   newid[NMAX];
  __align__(16) float rsum[2 * HDIM];
  __align__(16) float bvec[HDIM];
  __align__(16) float pvec[HDIM];
  __align__(16) float h1[HDIM];
  float red[4];
};

__device__ __forceinline__ unsigned long long make_key(float s, int idx) {
  unsigned bits = __float_as_uint(s);
  unsigned m = (bits & 0x80000000u) ? ~bits : (bits | 0x80000000u);
  unsigned hi = ~m;
  return ((unsigned long long)hi << 32) | (unsigned)idx;
}
__device__ __forceinline__ float key_score(unsigned long long k) {
  unsigned m = ~(unsigned)(k >> 32);
  unsigned bits = (m & 0x80000000u) ? (m ^ 0x80000000u) : ~m;
  return __uint_as_float(bits);
}

__device__ __forceinline__ unsigned long long ce_shfl(unsigned long long k, int j, bool takeMin) {
  unsigned long long o = __shfl_xor_sync(0xffffffffu, k, j);
  unsigned long long mn = (o < k) ? o : k;
  unsigned long long mx = (o < k) ? k : o;
  return takeMin ? mn : mx;
}

__device__ __forceinline__ void smem_ce(unsigned long long* a, int tid, int j, int ksz) {
  if (tid < 128) {
    int low = tid & (j - 1);
    int i = ((tid ^ low) << 1) | low;
    int p = i | j;
    unsigned long long x = a[i], y = a[p];
    bool asc = ((i & ksz) == 0);
    bool sw = asc ? (x > y) : (x < y);
    if (sw) { a[i] = y; a[p] = x; }
  }
}

// ---- GEMM: 4 rows x 4 cols per thread (1024 threads = 64 rowgrps x 16 colgrps)
__device__ __forceinline__ void gemm_epilogue(float* __restrict__ tmp, int row0, int n,
                                              int cbase, unsigned long long acc[4][2]) {
#pragma unroll
  for (int r = 0; r < 4; ++r) {
    const int row = row0 + r;
    if (row < n) {
      *reinterpret_cast<unsigned long long*>(&tmp[row * XS + cbase])     = acc[r][0];
      *reinterpret_cast<unsigned long long*>(&tmp[row * XS + cbase + 2]) = acc[r][1];
    }
  }
}

// layer 0 (K=39, plain input)
__device__ __forceinline__ void gemm_first(const float* __restrict__ cur,
                                           float* __restrict__ tmp,
                                           const float* __restrict__ Ws, int tid) {
  const int cbase = (tid & 15) * 4;
  const int row0  = (tid >> 4) * 4;
  unsigned long long acc[4][2];
#pragma unroll
  for (int r = 0; r < 4; ++r) { acc[r][0] = 0ull; acc[r][1] = 0ull; }
#pragma unroll 3
  for (int k = 0; k < EMBED; ++k) {
    const ulonglong2 w = *reinterpret_cast<const ulonglong2*>(&Ws[k * HDIM + cbase]);
#pragma unroll
    for (int r = 0; r < 4; ++r) {
      unsigned long long xa;
      DUP_F32(xa, cur[(row0 + r) * XS + k]);
      FMA_F32X2(acc[r][0], xa, w.x, acc[r][0]);
      FMA_F32X2(acc[r][1], xa, w.y, acc[r][1]);
    }
  }
  gemm_epilogue(tmp, row0, NMAX, cbase, acc);
}

// layers 1,2 (K=64, plain input, k-paired)
__device__ __forceinline__ void gemm_h(const float* __restrict__ cur,
                                       float* __restrict__ tmp,
                                       const float* __restrict__ Ws, int n, int tid) {
  const int cbase = (tid & 15) * 4;
  const int row0  = (tid >> 4) * 4;
  if (row0 >= n) return;
  unsigned long long acc[4][2];
#pragma unroll
  for (int r = 0; r < 4; ++r) { acc[r][0] = 0ull; acc[r][1] = 0ull; }
#pragma unroll 8
  for (int k2 = 0; k2 < 32; ++k2) {
    const ulonglong2 w0 = *reinterpret_cast<const ulonglong2*>(&Ws[(2 * k2)     * HDIM + cbase]);
    const ulonglong2 w1 = *reinterpret_cast<const ulonglong2*>(&Ws[(2 * k2 + 1) * HDIM + cbase]);
#pragma unroll
    for (int r = 0; r < 4; ++r) {
      const float2 xv = *reinterpret_cast<const float2*>(&cur[(row0 + r) * XS + 2 * k2]);
      unsigned long long xa, xb;
      DUP_F32(xa, xv.x);
      DUP_F32(xb, xv.y);
      FMA_F32X2(acc[r][0], xa, w0.x, acc[r][0]);
      FMA_F32X2(acc[r][1], xa, w0.y, acc[r][1]);
      FMA_F32X2(acc[r][0], xb, w1.x, acc[r][0]);
      FMA_F32X2(acc[r][1], xb, w1.y, acc[r][1]);
    }
  }
  gemm_epilogue(tmp, row0, n, cbase, acc);
}

__global__ __launch_bounds__(NT)
void gnn_kernel(const float* __restrict__ x,
                const int* __restrict__ ei,
                const float* __restrict__ W1, const float* __restrict__ b1, const float* __restrict__ p1,
                const float* __restrict__ W2, const float* __restrict__ b2, const float* __restrict__ p2,
                const float* __restrict__ W3, const float* __restrict__ b3, const float* __restrict__ p3,
                const float* __restrict__ lW1, const float* __restrict__ lb1,
                const float* __restrict__ lW2, const float* __restrict__ lb2,
                const float* __restrict__ lW3, const float* __restrict__ lb3,
                float* __restrict__ out) {
  extern __shared__ char smraw[];
  Smem& S = *reinterpret_cast<Smem*>(smraw);
  const int b    = blockIdx.x;
  const int tid  = threadIdx.x;
  const int lane = tid & 31;
  const int wid  = tid >> 5;
  const int hw   = tid >> 4;                         // half-warp unit 0..63
  const int hl   = tid & 15;                         // lane within half
  const unsigned hmask = 0xFFFFu << (tid & 16);      // shfl mask for this half

  // ---- edge load: 2 edges per thread ----
  const int* eb = ei + (size_t)b * 2 * EDGES;
  {
    const int2 s2 = *reinterpret_cast<const int2*>(&eb[tid * 2]);
    const int2 d2 = *reinterpret_cast<const int2*>(&eb[EDGES + tid * 2]);
    uint2 w;
    w.x = ((unsigned)s2.x & 255u) | (((unsigned)d2.x & 255u) << 8) | (1u << 16);
    w.y = ((unsigned)s2.y & 255u) | (((unsigned)d2.y & 255u) << 8) | (1u << 16);
    *reinterpret_cast<uint2*>(&S.epack[tid * 2]) = w;
  }
  // ---- stage x [256, 39] coalesced ----
  const float* xb = x + (size_t)b * NMAX * EMBED;
  for (int idx = tid; idx < NMAX * EMBED; idx += NT) {
    int r = idx / EMBED, c = idx - r * EMBED;
    S.xsA[r * XS + c] = xb[idx];
  }
  if (tid < 2 * HDIM) S.rsum[tid] = 0.f;

  float* cur = S.xsA;
  float* tmp = S.xsB;
  int n = NMAX;
  const int kk[3] = {205, 164, 132};
  const float* Wl[3] = {W1, W2, W3};
  const float* bl[3] = {b1, b2, b3};
  const float* pl[3] = {p1, p2, p3};

  for (int layer = 0; layer < 3; ++layer) {
    const int KD = (layer == 0) ? EMBED : HDIM;
    // ---- stage weights / bias / p / hist clear ----
    for (int idx = tid; idx < (KD * HDIM) / 4; idx += NT)
      reinterpret_cast<float4*>(S.Ws)[idx] = reinterpret_cast<const float4*>(Wl[layer])[idx];
    if (tid >= 64 && tid < 128) { int j = tid - 64; S.bvec[j] = bl[layer][j]; S.pvec[j] = pl[layer][j]; }
    if (tid >= 128 && tid < 384) S.hist[tid - 128] = 0;
    if (wid == 14) {  // pscale = 1/||p||
      float a = pl[layer][lane], c2 = pl[layer][lane + 32];
      float s2 = a * a + c2 * c2;
#pragma unroll
      for (int o = 16; o; o >>= 1) s2 += __shfl_xor_sync(0xffffffffu, s2, o);
      if (lane == 0) S.red[0] = rsqrtf(s2);
    }
    __syncthreads();

    // ---- GEMM (into tmp) + histogram of valid edges ----
    if (layer == 0) gemm_first(cur, tmp, S.Ws, tid);
    else            gemm_h(cur, tmp, S.Ws, n, tid);
#pragma unroll
    for (int e = tid; e < EDGES; e += NT) {
      unsigned u = S.epack[e];
      if (u >> 16) atomicAdd(&S.hist[(u >> 8) & 255], 1);
    }
    __syncthreads();

    // ---- single-warp scan -> ofs / cursor / dinv ----
    if (wid == 0) {
      int c[8];
#pragma unroll
      for (int q = 0; q < 8; ++q) c[q] = S.hist[lane * 8 + q];
      int sum = 0;
#pragma unroll
      for (int q = 0; q < 8; ++q) sum += c[q];
      int incl = sum;
#pragma unroll
      for (int o = 1; o < 32; o <<= 1) {
        int t = __shfl_up_sync(0xffffffffu, incl, o);
        if (lane >= o) incl += t;
      }
      int run = incl - sum;
#pragma unroll
      for (int q = 0; q < 8; ++q) {
        int node = lane * 8 + q;
        S.ofs[node]    = run;
        S.cursor[node] = run;
        S.dinv[node]   = rsqrtf(1.0f + (float)c[q]);
        run += c[q];
      }
      if (lane == 31) S.ofs[NMAX] = run;
    }
    __syncthreads();

    // ---- scatter valid edges (src only), sorted by dst ----
#pragma unroll
    for (int e = tid; e < EDGES; e += NT) {
      unsigned u = S.epack[e];
      if (u >> 16) {
        int d = (u >> 8) & 255;
        int pos = atomicAdd(&S.cursor[d], 1);
        S.esorted[pos] = u & 255u;
      }
    }
    __syncthreads();

    // ---- aggregation (half-warp per node) + relu + fused score ----
    const float pscale = S.red[0];
    for (int i = hw; i < n; i += NT / 16) {
      const int beg = S.ofs[i], end = S.ofs[i + 1];
      const float di = S.dinv[i];
      unsigned long long a01 = 0ull, a23 = 0ull;
      for (int p = beg; p < end; ++p) {
        const int sN = S.esorted[p];
        unsigned long long cp;
        DUP_F32(cp, S.dinv[sN]);
        const ulonglong2 hv =
            *reinterpret_cast<const ulonglong2*>(&tmp[sN * XS + hl * 4]);
        FMA_F32X2(a01, cp, hv.x, a01);
        FMA_F32X2(a23, cp, hv.y, a23);
      }
      float av[4];
      asm("mov.b64 {%0, %1}, %2;" : "=f"(av[0]), "=f"(av[1]) : "l"(a01));
      asm("mov.b64 {%0, %1}, %2;" : "=f"(av[2]), "=f"(av[3]) : "l"(a23));
      const float4 hs = *reinterpret_cast<const float4*>(&tmp[i * XS + hl * 4]);
      const float4 bv = *reinterpret_cast<const float4*>(&S.bvec[hl * 4]);
      const float4 pv = *reinterpret_cast<const float4*>(&S.pvec[hl * 4]);
      const float idg = di * di;
      float v0 = fmaxf(av[0] * di + hs.x * idg + bv.x, 0.f);
      float v1 = fmaxf(av[1] * di + hs.y * idg + bv.y, 0.f);
      float v2 = fmaxf(av[2] * di + hs.z * idg + bv.z, 0.f);
      float v3 = fmaxf(av[3] * di + hs.w * idg + bv.w, 0.f);
      float4 vv = {v0, v1, v2, v3};
      *reinterpret_cast<float4*>(&cur[i * XS + hl * 4]) = vv;
      float sc = v0 * pv.x + v1 * pv.y + v2 * pv.z + v3 * pv.w;
#pragma unroll
      for (int o = 8; o; o >>= 1) sc += __shfl_xor_sync(hmask, sc, o);
      if (hl == 0) S.skey64[i] = make_key(tanhf(sc * pscale), i);
    }
    for (int i = n + tid; i < NMAX; i += NT) S.skey64[i] = make_key(-1e30f, i);
    if (tid < NMAX) S.newid[tid] = -1;
    __syncthreads();

    // ---- bitonic sort 256 u64 keys (warp shuffle + smem merge) ----
    if (tid < NMAX) {
      unsigned long long k = S.skey64[tid];
#pragma unroll
      for (int ksz = 2; ksz <= 32; ksz <<= 1)
#pragma unroll
        for (int j = ksz >> 1; j > 0; j >>= 1)
          k = ce_shfl(k, j, ((tid & j) == 0) == ((tid & ksz) == 0));
      S.skey64[tid] = k;
    }
    __syncthreads();
#pragma unroll
    for (int ksz = 64; ksz <= 256; ksz <<= 1) {
      for (int j = ksz >> 1; j >= 32; j >>= 1) {
        smem_ce(S.skey64, tid, j, ksz);
        __syncthreads();
      }
      if (tid < NMAX) {
        unsigned long long k = S.skey64[tid];
        const bool asc = ((tid & ksz) == 0);
#pragma unroll
        for (int j = 16; j > 0; j >>= 1)
          k = ce_shfl(k, j, ((tid & j) == 0) == asc);
        S.skey64[tid] = k;
      }
      __syncthreads();
    }

    const int kcur = kk[layer];
    if (tid < kcur) {
      int old = (int)(S.skey64[tid] & 0xffffffffull);
      S.newid[old] = tid;
    }
    __syncthreads();

    // ---- pooled rows -> tmp (scaled, half-warp per rank); remap edges ----
    for (int r = hw; r < kcur; r += NT / 16) {
      unsigned long long key = S.skey64[r];
      int old = (int)(key & 0xffffffffull);
      float v = key_score(key);
      float4 h4 = *reinterpret_cast<const float4*>(&cur[old * XS + hl * 4]);
      h4.x *= v; h4.y *= v; h4.z *= v; h4.w *= v;
      *reinterpret_cast<float4*>(&tmp[r * XS + hl * 4]) = h4;
    }
    if (layer < 2) {
#pragma unroll
      for (int e = tid; e < EDGES; e += NT) {
        unsigned u = S.epack[e];
        int sN = u & 255, d = (u >> 8) & 255;
        int valid = (int)(u >> 16);
        int ns = S.newid[sN], nd = S.newid[d];
        int nv = (valid && ns >= 0 && nd >= 0) ? 1 : 0;
        if (ns < 0) ns = 0;
        if (nd < 0) nd = 0;
        S.epack[e] = (unsigned)ns | ((unsigned)nd << 8) | ((unsigned)nv << 16);
      }
    }
    __syncthreads();

    // ---- readout: warp per column ----
    for (int c = wid; c < HDIM; c += NT / 32) {
      float m = -1e30f, sm = 0.f;
      for (int r = lane; r < kcur; r += 32) {
        float v = tmp[r * XS + c];
        m = fmaxf(m, v);
        sm += v;
      }
#pragma unroll
      for (int o = 16; o; o >>= 1) {
        m  = fmaxf(m, __shfl_xor_sync(0xffffffffu, m, o));
        sm += __shfl_xor_sync(0xffffffffu, sm, o);
      }
      if (lane == 0) {
        S.rsum[c]        += m;
        S.rsum[HDIM + c] += sm / (float)kcur;
      }
    }
    float* t = cur; cur = tmp; tmp = t;
    n = kcur;
    __syncthreads();
  }

  // ---- MLP head: 128 -> 64 (256 threads) -> 32 -> 1 ----
  if (tid < 256) {
    int j = tid >> 2, q = tid & 3;
    float a = 0.f;
#pragma unroll 8
    for (int i = q * 32; i < q * 32 + 32; ++i) a += S.rsum[i] * lW1[i * 64 + j];
    a += __shfl_xor_sync(0xffffffffu, a, 1);
    a += __shfl_xor_sync(0xffffffffu, a, 2);
    if (q == 0) S.h1[j] = fmaxf(a + lb1[j], 0.f);
  }
  __syncthreads();
  if (tid < 32) {
    float a = lb2[tid];
#pragma unroll 8
    for (int j = 0; j < 64; ++j) a += S.h1[j] * lW2[j * 32 + tid];
    float h2 = fmaxf(a, 0.f);
    float v = h2 * lW3[tid];
#pragma unroll
    for (int o = 16; o; o >>= 1) v += __shfl_xor_sync(0xffffffffu, v, o);
    if (tid == 0) out[b] = 1.0f / (1.0f + expf(-(v + lb3[0])));
  }
}

extern "C" void kernel_launch(void* const* d_in, const int* in_sizes, int n_in,
                              void* d_out, int out_size) {
  const float* x   = (const float*)d_in[0];
  const int*   ei  = (const int*)d_in[1];
  const float* W1  = (const float*)d_in[2];
  const float* b1  = (const float*)d_in[3];
  const float* p1  = (const float*)d_in[4];
  const float* W2  = (const float*)d_in[5];
  const float* b2  = (const float*)d_in[6];
  const float* p2  = (const float*)d_in[7];
  const float* W3  = (const float*)d_in[8];
  const float* b3  = (const float*)d_in[9];
  const float* p3  = (const float*)d_in[10];
  const float* lW1 = (const float*)d_in[11];
  const float* lb1 = (const float*)d_in[12];
  const float* lW2 = (const float*)d_in[13];
  const float* lb2 = (const float*)d_in[14];
  const float* lW3 = (const float*)d_in[15];
  const float* lb3 = (const float*)d_in[16];
  float* out = (float*)d_out;

  const int B = in_sizes[0] / (NMAX * EMBED);
  const size_t sm = sizeof(Smem);
  cudaFuncSetAttribute(gnn_kernel, cudaFuncAttributeMaxDynamicSharedMemorySize, (int)sm);
  gnn_kernel<<<B, NT, sm>>>(x, ei, W1, b1, p1, W2, b2, p2, W3, b3, p3,
                            lW1, lb1, lW2, lb2, lW3, lb3, out);
}